// round 8
// baseline (speedup 1.0000x reference)
#include <cuda_runtime.h>
#include <math.h>

// FINAL (converged) — launch-latency-floor kernel; see R1-R7 journal.
// Wins: dense O(G^2) exp kernel -> O(G) fwd/bwd linear recurrence (R1);
//       fp64 exp -> fp32 (R2, 2.6x). All later probes neutral/regression.
// Problem constants (from reference): G=4096 grid, C=8 channels, N=4 batch.
constexpr int G  = 4096;
constexpr int C  = 8;
constexpr int NB = 4;
constexpr int T  = 256;        // threads per block
constexpr int L  = G / T;      // 16 elements per thread
constexpr int WARPS = T / 32;  // 8

// out[n,c,i] = 0.5*a_c*dx * sum_j d[n,j] * exp(-|i-j|*dx*a_c)
// a_c = 1/sigmoid(xi_c) = 1 + exp(-xi_c)
// Forward/backward first-order linear recurrences with ratio r = exp(-dx*a),
// 3-level segmented scan (thread chunk -> warp shfl scan -> cross-warp smem).
// __expf (MUFU.EX2) is safe here: all exponent args have |x| <= ~0.25.
__global__ __launch_bounds__(T, 1)
void gconv_scan_kernel(const float* __restrict__ density,
                       const float* __restrict__ xi,
                       const float* __restrict__ grid,
                       float* __restrict__ out)
{
    const int nc   = blockIdx.x;        // 0..N*C-1
    const int n    = nc / C;
    const int c    = nc % C;
    const int tid  = threadIdx.x;
    const int lane = tid & 31;
    const int warp = tid >> 5;

    __shared__ float sWf[WARPS];
    __shared__ float sWb[WARPS];

    // ---- issue density loads FIRST so DRAM latency overlaps constant setup ----
    const float4* d4 = (const float4*)(density + (size_t)n * G + (size_t)tid * L);
    float4 v0 = d4[0], v1 = d4[1], v2 = d4[2], v3 = d4[3];

    // ---- scalar setup (fast intrinsics; args tiny so EX2 approx is ~2^-22 rel) ----
    const float dx   = grid[1] - grid[0];
    const float a    = 1.0f + __expf(-xi[c]);    // xi_eff = 1/sigmoid(xi)
    const float dxa  = dx * a;
    const float r    = __expf(-dxa);                         // r^1
    const float RL   = __expf(-dxa * (float)L);              // r^L
    const float R32L = __expf(-dxa * (float)(32 * L));       // r^{32L}
    // bridge powers for carry injection (direct, no product drift)
    const float pf = __expf(-dxa * (float)(lane * L));
    const float pb = __expf(-dxa * (float)((31 - lane) * L));

    float d[L];
    d[0]=v0.x; d[1]=v0.y; d[2]=v0.z; d[3]=v0.w;
    d[4]=v1.x; d[5]=v1.y; d[6]=v1.z; d[7]=v1.w;
    d[8]=v2.x; d[9]=v2.y; d[10]=v2.z; d[11]=v2.w;
    d[12]=v3.x; d[13]=v3.y; d[14]=v3.z; d[15]=v3.w;

    // ---- local (per-thread) forward and backward scans (two independent chains) ----
    float lf[L], lb[L];
    {
        float s = 0.f;
        #pragma unroll
        for (int k = 0; k < L; k++) { s = fmaf(r, s, d[k]); lf[k] = s; }
    }
    {
        float s = 0.f;
        #pragma unroll
        for (int k = L - 1; k >= 0; k--) { s = fmaf(r, s, d[k]); lb[k] = s; }
    }

    // ---- warp-level inclusive scans of chunk aggregates (ratio RL) ----
    float vf = lf[L - 1];   // forward aggregate of this chunk
    float vb = lb[0];       // backward aggregate of this chunk
    float Rp = RL;
    #pragma unroll
    for (int off = 1; off < 32; off <<= 1) {
        float uf = __shfl_up_sync(0xffffffffu, vf, off);
        float ub = __shfl_down_sync(0xffffffffu, vb, off);
        if (lane >= off)      vf = fmaf(Rp, uf, vf);
        if (lane < 32 - off)  vb = fmaf(Rp, ub, vb);
        Rp *= Rp;  // RL^{2^i}
    }

    if (lane == 31) sWf[warp] = vf;   // whole-warp forward aggregate
    if (lane == 0)  sWb[warp] = vb;   // whole-warp backward aggregate
    __syncthreads();

    // ---- cross-warp carries (<= 8 serial fma's, computed redundantly per thread) ----
    float cwf = 0.f;
    #pragma unroll
    for (int u = 0; u < WARPS; u++)
        if (u < warp) cwf = fmaf(R32L, cwf, sWf[u]);
    float cwb = 0.f;
    #pragma unroll
    for (int u = WARPS - 1; u >= 0; u--)
        if (u > warp) cwb = fmaf(R32L, cwb, sWb[u]);

    // exclusive within-warp prefixes
    float ef = __shfl_up_sync(0xffffffffu, vf, 1);
    if (lane == 0)  ef = 0.f;
    float eb = __shfl_down_sync(0xffffffffu, vb, 1);
    if (lane == 31) eb = 0.f;

    const float carryF = fmaf(pf, cwf, ef);  // S_f at (chunk base - 1)
    const float carryB = fmaf(pb, cwb, eb);  // S_b at (chunk base + L)

    // ---- apply carries: S_f[k] += r^{k+1}*carryF ; S_b[k] += r^{L-k}*carryB ----
    {
        float w = r;
        #pragma unroll
        for (int k = 0; k < L; k++) { lf[k] = fmaf(w, carryF, lf[k]); w *= r; }
    }
    {
        float w = r;
        #pragma unroll
        for (int k = L - 1; k >= 0; k--) { lb[k] = fmaf(w, carryB, lb[k]); w *= r; }
    }

    // ---- combine + write (128-bit stores) ----
    const float scale = 0.5f * a * dx;
    float4* optr = (float4*)(out + (size_t)nc * G + (size_t)tid * L);
    #pragma unroll
    for (int q = 0; q < L / 4; q++) {
        float4 v;
        v.x = scale * (lf[4*q+0] + lb[4*q+0] - d[4*q+0]);
        v.y = scale * (lf[4*q+1] + lb[4*q+1] - d[4*q+1]);
        v.z = scale * (lf[4*q+2] + lb[4*q+2] - d[4*q+2]);
        v.w = scale * (lf[4*q+3] + lb[4*q+3] - d[4*q+3]);
        optr[q] = v;
    }
}

extern "C" void kernel_launch(void* const* d_in, const int* in_sizes, int n_in,
                              void* d_out, int out_size)
{
    const float* density = (const float*)d_in[0];  // (N,1,G)
    const float* xi      = (const float*)d_in[1];  // (C,)
    const float* grid    = (const float*)d_in[2];  // (G,)
    float*       out     = (float*)d_out;          // (N,C,G)

    gconv_scan_kernel<<<NB * C, T>>>(density, xi, grid, out);
}

// round 9
// speedup vs baseline: 1.0437x; 1.0437x over previous
#include <cuda_runtime.h>
#include <math.h>

// FINAL (converged, 4x reproduced) — launch-latency-floor kernel; R1-R8 journal.
// Wins: dense O(G^2) exp kernel -> O(G) fwd/bwd linear recurrence (R1);
//       fp64 exp -> fp32 (R2, 2.6x). All later probes neutral/regression.
// Problem constants (from reference): G=4096 grid, C=8 channels, N=4 batch.
constexpr int G  = 4096;
constexpr int C  = 8;
constexpr int NB = 4;
constexpr int T  = 256;        // threads per block
constexpr int L  = G / T;      // 16 elements per thread
constexpr int WARPS = T / 32;  // 8

// out[n,c,i] = 0.5*a_c*dx * sum_j d[n,j] * exp(-|i-j|*dx*a_c)
// a_c = 1/sigmoid(xi_c) = 1 + exp(-xi_c)
// Forward/backward first-order linear recurrences with ratio r = exp(-dx*a),
// 3-level segmented scan (thread chunk -> warp shfl scan -> cross-warp smem).
// __expf (MUFU.EX2) is safe here: all exponent args have |x| <= ~0.25.
__global__ __launch_bounds__(T, 1)
void gconv_scan_kernel(const float* __restrict__ density,
                       const float* __restrict__ xi,
                       const float* __restrict__ grid,
                       float* __restrict__ out)
{
    const int nc   = blockIdx.x;        // 0..N*C-1
    const int n    = nc / C;
    const int c    = nc % C;
    const int tid  = threadIdx.x;
    const int lane = tid & 31;
    const int warp = tid >> 5;

    __shared__ float sWf[WARPS];
    __shared__ float sWb[WARPS];

    // ---- issue density loads FIRST so DRAM latency overlaps constant setup ----
    const float4* d4 = (const float4*)(density + (size_t)n * G + (size_t)tid * L);
    float4 v0 = d4[0], v1 = d4[1], v2 = d4[2], v3 = d4[3];

    // ---- scalar setup (fast intrinsics; args tiny so EX2 approx is ~2^-22 rel) ----
    const float dx   = grid[1] - grid[0];
    const float a    = 1.0f + __expf(-xi[c]);    // xi_eff = 1/sigmoid(xi)
    const float dxa  = dx * a;
    const float r    = __expf(-dxa);                         // r^1
    const float RL   = __expf(-dxa * (float)L);              // r^L
    const float R32L = __expf(-dxa * (float)(32 * L));       // r^{32L}
    // bridge powers for carry injection (direct, no product drift)
    const float pf = __expf(-dxa * (float)(lane * L));
    const float pb = __expf(-dxa * (float)((31 - lane) * L));

    float d[L];
    d[0]=v0.x; d[1]=v0.y; d[2]=v0.z; d[3]=v0.w;
    d[4]=v1.x; d[5]=v1.y; d[6]=v1.z; d[7]=v1.w;
    d[8]=v2.x; d[9]=v2.y; d[10]=v2.z; d[11]=v2.w;
    d[12]=v3.x; d[13]=v3.y; d[14]=v3.z; d[15]=v3.w;

    // ---- local (per-thread) forward and backward scans (two independent chains) ----
    float lf[L], lb[L];
    {
        float s = 0.f;
        #pragma unroll
        for (int k = 0; k < L; k++) { s = fmaf(r, s, d[k]); lf[k] = s; }
    }
    {
        float s = 0.f;
        #pragma unroll
        for (int k = L - 1; k >= 0; k--) { s = fmaf(r, s, d[k]); lb[k] = s; }
    }

    // ---- warp-level inclusive scans of chunk aggregates (ratio RL) ----
    float vf = lf[L - 1];   // forward aggregate of this chunk
    float vb = lb[0];       // backward aggregate of this chunk
    float Rp = RL;
    #pragma unroll
    for (int off = 1; off < 32; off <<= 1) {
        float uf = __shfl_up_sync(0xffffffffu, vf, off);
        float ub = __shfl_down_sync(0xffffffffu, vb, off);
        if (lane >= off)      vf = fmaf(Rp, uf, vf);
        if (lane < 32 - off)  vb = fmaf(Rp, ub, vb);
        Rp *= Rp;  // RL^{2^i}
    }

    if (lane == 31) sWf[warp] = vf;   // whole-warp forward aggregate
    if (lane == 0)  sWb[warp] = vb;   // whole-warp backward aggregate
    __syncthreads();

    // ---- cross-warp carries (<= 8 serial fma's, computed redundantly per thread) ----
    float cwf = 0.f;
    #pragma unroll
    for (int u = 0; u < WARPS; u++)
        if (u < warp) cwf = fmaf(R32L, cwf, sWf[u]);
    float cwb = 0.f;
    #pragma unroll
    for (int u = WARPS - 1; u >= 0; u--)
        if (u > warp) cwb = fmaf(R32L, cwb, sWb[u]);

    // exclusive within-warp prefixes
    float ef = __shfl_up_sync(0xffffffffu, vf, 1);
    if (lane == 0)  ef = 0.f;
    float eb = __shfl_down_sync(0xffffffffu, vb, 1);
    if (lane == 31) eb = 0.f;

    const float carryF = fmaf(pf, cwf, ef);  // S_f at (chunk base - 1)
    const float carryB = fmaf(pb, cwb, eb);  // S_b at (chunk base + L)

    // ---- apply carries: S_f[k] += r^{k+1}*carryF ; S_b[k] += r^{L-k}*carryB ----
    {
        float w = r;
        #pragma unroll
        for (int k = 0; k < L; k++) { lf[k] = fmaf(w, carryF, lf[k]); w *= r; }
    }
    {
        float w = r;
        #pragma unroll
        for (int k = L - 1; k >= 0; k--) { lb[k] = fmaf(w, carryB, lb[k]); w *= r; }
    }

    // ---- combine + write (128-bit stores) ----
    const float scale = 0.5f * a * dx;
    float4* optr = (float4*)(out + (size_t)nc * G + (size_t)tid * L);
    #pragma unroll
    for (int q = 0; q < L / 4; q++) {
        float4 v;
        v.x = scale * (lf[4*q+0] + lb[4*q+0] - d[4*q+0]);
        v.y = scale * (lf[4*q+1] + lb[4*q+1] - d[4*q+1]);
        v.z = scale * (lf[4*q+2] + lb[4*q+2] - d[4*q+2]);
        v.w = scale * (lf[4*q+3] + lb[4*q+3] - d[4*q+3]);
        optr[q] = v;
    }
}

extern "C" void kernel_launch(void* const* d_in, const int* in_sizes, int n_in,
                              void* d_out, int out_size)
{
    const float* density = (const float*)d_in[0];  // (N,1,G)
    const float* xi      = (const float*)d_in[1];  // (C,)
    const float* grid    = (const float*)d_in[2];  // (G,)
    float*       out     = (float*)d_out;          // (N,C,G)

    gconv_scan_kernel<<<NB * C, T>>>(density, xi, grid, out);
}